// round 16
// baseline (speedup 1.0000x reference)
#include <cuda_runtime.h>
#include <cuda_fp16.h>
#include <stdint.h>
#include <math.h>

#define L_   4096
#define DM_  1024
#define H_   16
#define DH_  64
#define BS_  64
#define W_   16
#define NB_  64
#define DFF_ 4096

// ---------------- scratch (static __device__ arrays; no allocations) ----------------
__device__ __half g_H [L_ * DM_];
__device__ __half g_Q [L_ * DM_];
__device__ __half g_K [L_ * DM_];
__device__ __half g_V [L_ * DM_];
__device__ __half g_O [L_ * DM_];
__device__ float  g_X1[L_ * DM_];
__device__ __half g_G [L_ * DFF_];
__device__ __half g_WqH[DM_ * DM_];
__device__ __half g_WkH[DM_ * DM_];
__device__ __half g_WvH[DM_ * DM_];
__device__ __half g_WoH[DM_ * DM_];
__device__ __half g_W1H[DM_ * DFF_];
__device__ __half g_W2H[DFF_ * DM_];
// split-KV attention partials
__device__ float g_OP[2 * L_ * DM_];
__device__ float g_Mp[2 * H_ * L_];
__device__ float g_Lp[2 * H_ * L_];

// ---------------- small helpers ----------------
__device__ __forceinline__ float block_sum(float val, float* red) {
    int t = threadIdx.x;
    #pragma unroll
    for (int o = 16; o > 0; o >>= 1) val += __shfl_xor_sync(0xffffffffu, val, o);
    __syncthreads();
    if ((t & 31) == 0) red[t >> 5] = val;
    __syncthreads();
    if (t == 0) {
        float z = 0.f;
        #pragma unroll
        for (int i = 0; i < 8; i++) z += red[i];
        red[0] = z;
    }
    __syncthreads();
    return red[0];
}

__device__ __forceinline__ float gelu_f(float x) {
    float x3 = x * x * x;
    return 0.5f * x * (1.f + tanhf(0.7978845608028654f * (x + 0.044715f * x3)));
}

__device__ __forceinline__ void mma_f16(float* d, const unsigned* a, unsigned b0, unsigned b1) {
    asm volatile(
        "mma.sync.aligned.m16n8k16.row.col.f32.f16.f16.f32 "
        "{%0,%1,%2,%3}, {%4,%5,%6,%7}, {%8,%9}, {%0,%1,%2,%3};\n"
        : "+f"(d[0]), "+f"(d[1]), "+f"(d[2]), "+f"(d[3])
        : "r"(a[0]), "r"(a[1]), "r"(a[2]), "r"(a[3]), "r"(b0), "r"(b1));
}

__device__ __forceinline__ void ldsm_x4(unsigned& r0, unsigned& r1, unsigned& r2, unsigned& r3,
                                        uint32_t addr) {
    asm volatile("ldmatrix.sync.aligned.m8n8.x4.shared.b16 {%0,%1,%2,%3}, [%4];"
                 : "=r"(r0), "=r"(r1), "=r"(r2), "=r"(r3) : "r"(addr));
}
__device__ __forceinline__ void ldsm_x4_t(unsigned& r0, unsigned& r1, unsigned& r2, unsigned& r3,
                                          uint32_t addr) {
    asm volatile("ldmatrix.sync.aligned.m8n8.x4.trans.shared.b16 {%0,%1,%2,%3}, [%4];"
                 : "=r"(r0), "=r"(r1), "=r"(r2), "=r"(r3) : "r"(addr));
}

__device__ __forceinline__ uint32_t s2u(const void* p) {
    return (uint32_t)__cvta_generic_to_shared(p);
}

__device__ __forceinline__ void cp16(uint32_t dst, const void* src) {
    asm volatile("cp.async.cg.shared.global [%0], [%1], 16;" :: "r"(dst), "l"(src));
}

__device__ __forceinline__ uint32_t pack_h2(float lo, float hi) {
    __half2 h = __floats2half2_rn(lo, hi);
    return *reinterpret_cast<uint32_t*>(&h);
}

// ---------------- LayerNorm body (shared by prep + ln_kernel) ----------------
__device__ __forceinline__ void ln_row(const float* __restrict__ x,
                                       const float* __restrict__ g,
                                       const float* __restrict__ b,
                                       __half* __restrict__ out, int row, float* red) {
    const float* xr = x + (size_t)row * DM_;
    int t = threadIdx.x;
    float v[4];
    float s = 0.f;
    #pragma unroll
    for (int i = 0; i < 4; i++) { v[i] = xr[t + i * 256]; s += v[i]; }
    float mean = block_sum(s, red) * (1.f / DM_);
    float s2 = 0.f;
    #pragma unroll
    for (int i = 0; i < 4; i++) { float d = v[i] - mean; s2 += d * d; }
    float var = block_sum(s2, red) * (1.f / DM_);
    float inv = rsqrtf(var + 1e-5f);
    __half* orow = out + (size_t)row * DM_;
    #pragma unroll
    for (int i = 0; i < 4; i++) {
        int c = t + i * 256;
        orow[c] = __float2half((v[i] - mean) * inv * g[c] + b[c]);
    }
}

__global__ __launch_bounds__(256) void ln_kernel(const float* __restrict__ x,
                                                 const float* __restrict__ g,
                                                 const float* __restrict__ b,
                                                 __half* __restrict__ out) {
    __shared__ float red[8];
    ln_row(x, g, b, out, blockIdx.x, red);
}

// ---------------- fused prep: LN1 (blocks < L_) + weight cvt (blocks >= L_) ----------
#define SMALL8 (DM_ * DM_ / 8)
#define CVT_BLOCKS (12 * SMALL8 / 256)
__global__ __launch_bounds__(256) void prep(
        const float* __restrict__ x, const float* __restrict__ g1,
        const float* __restrict__ b1g, __half* __restrict__ Hout,
        const float* __restrict__ s0, const float* __restrict__ s1,
        const float* __restrict__ s2, const float* __restrict__ s3,
        const float* __restrict__ s4, const float* __restrict__ s5,
        __half* __restrict__ d0, __half* __restrict__ d1,
        __half* __restrict__ d2, __half* __restrict__ d3,
        __half* __restrict__ d4, __half* __restrict__ d5) {
    __shared__ float red[8];
    if (blockIdx.x < L_) {
        ln_row(x, g1, b1g, Hout, blockIdx.x, red);
        return;
    }
    long i = (long)(blockIdx.x - L_) * 256 + threadIdx.x;
    const float* src; __half* dst; long off;
    if      (i < 1 * SMALL8)  { src = s0; dst = d0; off = i; }
    else if (i < 2 * SMALL8)  { src = s1; dst = d1; off = i - 1 * SMALL8; }
    else if (i < 3 * SMALL8)  { src = s2; dst = d2; off = i - 2 * SMALL8; }
    else if (i < 4 * SMALL8)  { src = s3; dst = d3; off = i - 3 * SMALL8; }
    else if (i < 8 * SMALL8)  { src = s4; dst = d4; off = i - 4 * SMALL8; }
    else                      { src = s5; dst = d5; off = i - 8 * SMALL8; }
    long e = off * 8;
    float4 a = *(const float4*)(src + e);
    float4 b = *(const float4*)(src + e + 4);
    uint4 o;
    o.x = pack_h2(a.x, a.y); o.y = pack_h2(a.z, a.w);
    o.z = pack_h2(b.x, b.y); o.w = pack_h2(b.z, b.w);
    *(uint4*)(dst + e) = o;
}

// ---------------- ldmatrix fp16 GEMM, BK=64, 256 thr, warp tile 32x64 ----------------
#define A_STAGE_BYTES (128 * 144)
#define B_STAGE_BYTES (64 * 272)
#define STAGE_BYTES (A_STAGE_BYTES + B_STAGE_BYTES)
#define PIPE_SMEM (3 * STAGE_BYTES)

template<bool BIAS, bool RES, bool GELU_, bool HOUT>
__global__ __launch_bounds__(256, 2) void hgemm_pipe(
        const __half* __restrict__ A,
        const __half* __restrict__ B0, const __half* __restrict__ B1, const __half* __restrict__ B2,
        void* __restrict__ C0, void* __restrict__ C1, void* __restrict__ C2,
        const float* __restrict__ bias,
        const float* __restrict__ res,
        int M, int N, int K) {
    extern __shared__ char smem_c[];
    uint32_t sb = s2u(smem_c);

    int tid  = threadIdx.x;
    int lane = tid & 31;
    int wid  = tid >> 5;
    int bm = blockIdx.y * 128, bn = blockIdx.x * 128;
    int wm = wid >> 1, wn = wid & 1;
    int r = lane >> 2, c = lane & 3;

    const __half* B = (blockIdx.z == 0) ? B0 : (blockIdx.z == 1) ? B1 : B2;
    void*         C = (blockIdx.z == 0) ? C0 : (blockIdx.z == 1) ? C1 : C2;

    float acc[2][8][4];
    #pragma unroll
    for (int fm = 0; fm < 2; fm++)
        #pragma unroll
        for (int fn = 0; fn < 8; fn++)
            #pragma unroll
            for (int i = 0; i < 4; i++) acc[fm][fn][i] = 0.f;

    int NIT = K >> 6;

    auto issue = [&](int it) {
        uint32_t base = sb + (uint32_t)(it % 3) * STAGE_BYTES;
        int k0 = it << 6;
        #pragma unroll
        for (int p = 0; p < 4; p++) {
            int idx = p * 256 + tid;
            int row = idx >> 3, aq = idx & 7;
            cp16(base + (uint32_t)(row * 144 + aq * 16),
                 A + (size_t)(bm + row) * K + k0 + aq * 8);
        }
        #pragma unroll
        for (int p = 0; p < 4; p++) {
            int idx = p * 256 + tid;
            int row = idx >> 4, nq = idx & 15;
            cp16(base + (uint32_t)(A_STAGE_BYTES + row * 272 + nq * 16),
                 B + (size_t)(k0 + row) * N + bn + nq * 8);
        }
        asm volatile("cp.async.commit_group;" ::: "memory");
    };

    issue(0);
    issue(1);

    int tr = lane & 7;
    int q1 = (lane >> 3) & 1;
    int q2 = lane >> 4;

    for (int it = 0; it < NIT; it++) {
        asm volatile("cp.async.wait_group 1;" ::: "memory");
        __syncthreads();
        if (it + 2 < NIT) issue(it + 2);
        else asm volatile("cp.async.commit_group;" ::: "memory");

        uint32_t abase = sb + (uint32_t)(it % 3) * STAGE_BYTES;
        uint32_t bbase = abase + A_STAGE_BYTES;

        #pragma unroll
        for (int kt = 0; kt < 4; kt++) {
            unsigned af[2][4], bf[8][2];
            #pragma unroll
            for (int fm = 0; fm < 2; fm++) {
                int row = wm * 32 + fm * 16 + tr + q1 * 8;
                int colh = kt * 16 + q2 * 8;
                ldsm_x4(af[fm][0], af[fm][1], af[fm][2], af[fm][3],
                        abase + (uint32_t)(row * 144 + colh * 2));
            }
            #pragma unroll
            for (int fn2 = 0; fn2 < 4; fn2++) {
                int kk = kt * 16 + tr + q1 * 8;
                int nn = wn * 64 + fn2 * 16 + q2 * 8;
                ldsm_x4_t(bf[fn2 * 2][0], bf[fn2 * 2][1], bf[fn2 * 2 + 1][0], bf[fn2 * 2 + 1][1],
                          bbase + (uint32_t)(kk * 272 + nn * 2));
            }
            #pragma unroll
            for (int fm = 0; fm < 2; fm++)
                #pragma unroll
                for (int fn = 0; fn < 8; fn++)
                    mma_f16(acc[fm][fn], af[fm], bf[fn][0], bf[fn][1]);
        }
    }

    // epilogue
    #pragma unroll
    for (int fm = 0; fm < 2; fm++) {
        int r_lo = bm + wm * 32 + fm * 16 + r;
        #pragma unroll
        for (int fn = 0; fn < 8; fn++) {
            int col = bn + wn * 64 + fn * 8 + 2 * c;
            float v0 = acc[fm][fn][0], v1 = acc[fm][fn][1];
            float v2 = acc[fm][fn][2], v3 = acc[fm][fn][3];
            if (BIAS) {
                float b0v = bias[col], b1v = bias[col + 1];
                v0 += b0v; v1 += b1v; v2 += b0v; v3 += b1v;
            }
            if (GELU_) { v0 = gelu_f(v0); v1 = gelu_f(v1); v2 = gelu_f(v2); v3 = gelu_f(v3); }
            if (RES) {
                float2 r0 = *(const float2*)(res + (size_t)r_lo * N + col);
                float2 r1 = *(const float2*)(res + (size_t)(r_lo + 8) * N + col);
                v0 += r0.x; v1 += r0.y; v2 += r1.x; v3 += r1.y;
            }
            if (HOUT) {
                __half* Ch = (__half*)C;
                *(uint32_t*)(Ch + (size_t)r_lo * N + col)       = pack_h2(v0, v1);
                *(uint32_t*)(Ch + (size_t)(r_lo + 8) * N + col) = pack_h2(v2, v3);
            } else {
                float* Cf = (float*)C;
                *(float2*)(Cf + (size_t)r_lo * N + col)       = make_float2(v0, v1);
                *(float2*)(Cf + (size_t)(r_lo + 8) * N + col) = make_float2(v2, v3);
            }
        }
    }
}

// ---------------- split-KV banded attention: Q staged via K-buf0, 5 CTAs/SM ----------
#define SP_BYTES 144
#define TILE_BYTES (64 * SP_BYTES)
#define K_OFF  0
#define V_OFF  (TILE_BYTES * 2)
#define BIAS_OFF (TILE_BYTES * 4)
#define ATTN_SMEM (BIAS_OFF + 258 * 4)
#define LOG2E 1.4426950408889634f
#define SCALE_LOG2 (0.125f * LOG2E)

__global__ __launch_bounds__(128, 5) void attn_h(const __half* __restrict__ Q,
                                                 const __half* __restrict__ Kb,
                                                 const __half* __restrict__ Vb,
                                                 const float* __restrict__ rel_emb,
                                                 float* __restrict__ OP,
                                                 float* __restrict__ Mp,
                                                 float* __restrict__ Lp) {
    extern __shared__ char sm[];
    uint32_t sb = s2u(sm);
    float* bias_s = (float*)(sm + BIAS_OFF);

    int n = blockIdx.x, h = blockIdx.y, z = blockIdx.z;
    int tid = threadIdx.x, lane = tid & 31, wid = tid >> 5;
    int r = lane >> 2, c = lane & 3;
    int tr = lane & 7, q1 = (lane >> 3) & 1, q2 = lane >> 4;

    int w0full = (n >= W_ - 1) ? 0 : (W_ - 1 - n);
    int count = W_ - w0full;
    int half = count >> 1;
    int lo = (z == 0) ? w0full : (w0full + half);
    int hi = (z == 0) ? (w0full + half) : W_;

    int row0 = wid * 16 + r;
    float* Mz = Mp + (size_t)z * H_ * L_ + (size_t)h * L_ + n * 64;
    float* Lz = Lp + (size_t)z * H_ * L_ + (size_t)h * L_ + n * 64;

    if (lo >= hi) {
        if (c == 0) {
            Mz[row0] = -1e30f;     Lz[row0] = 0.f;
            Mz[row0 + 8] = -1e30f; Lz[row0 + 8] = 0.f;
        }
        return;
    }

    // stage Q through K buffer 0
    #pragma unroll
    for (int p = 0; p < 4; p++) {
        int idx = p * 128 + tid;
        int row = idx >> 3, nq = idx & 7;
        cp16(sb + K_OFF + (uint32_t)(row * SP_BYTES + nq * 16),
             Q + (size_t)(n * 64 + row) * DM_ + h * 64 + nq * 8);
    }
    asm volatile("cp.async.commit_group;" ::: "memory");
    for (int t = tid; t < 258; t += 128) bias_s[t] = rel_emb[t * H_ + h] * LOG2E;
    asm volatile("cp.async.wait_group 0;" ::: "memory");
    __syncthreads();

    // persistent Q fragments from K-buf0
    unsigned qf[4][4];
    {
        int arow = wid * 16 + tr + q1 * 8;
        #pragma unroll
        for (int kt = 0; kt < 4; kt++) {
            int colh = kt * 16 + q2 * 8;
            ldsm_x4(qf[kt][0], qf[kt][1], qf[kt][2], qf[kt][3],
                    sb + K_OFF + (uint32_t)(arow * SP_BYTES + colh * 2));
        }
    }
    __syncthreads();   // all warps done reading K-buf0 before KV pipeline overwrites it

    auto issueKV = [&](int w, int b) {
        int sbk = n - (W_ - 1) + w;
        const __half* kp = Kb + (size_t)(sbk * 64) * DM_ + h * 64;
        const __half* vp = Vb + (size_t)(sbk * 64) * DM_ + h * 64;
        uint32_t kb = sb + K_OFF + (uint32_t)b * TILE_BYTES;
        uint32_t vb = sb + V_OFF + (uint32_t)b * TILE_BYTES;
        #pragma unroll
        for (int p = 0; p < 4; p++) {
            int idx = p * 128 + tid;
            int row = idx >> 3, nq = idx & 7;
            cp16(kb + (uint32_t)(row * SP_BYTES + nq * 16), kp + (size_t)row * DM_ + nq * 8);
            cp16(vb + (uint32_t)(row * SP_BYTES + nq * 16), vp + (size_t)row * DM_ + nq * 8);
        }
        asm volatile("cp.async.commit_group;" ::: "memory");
    };

    issueKV(lo, 0);
    asm volatile("cp.async.wait_group 0;" ::: "memory");
    __syncthreads();

    float of[8][4];
    #pragma unroll
    for (int f = 0; f < 8; f++)
        #pragma unroll
        for (int e = 0; e < 4; e++) of[f][e] = 0.f;
    float m0 = -1e30f, m1 = -1e30f, l0 = 0.f, l1 = 0.f;

    int buf = 0;
    float cb = bias_s[257];

    for (int w = lo; w < hi; w++) {
        if (w + 1 < hi) issueKV(w + 1, buf ^ 1);
        uint32_t kbase = sb + K_OFF + (uint32_t)buf * TILE_BYTES;
        uint32_t vbase = sb + V_OFF + (uint32_t)buf * TILE_BYTES;

        // S = Q @ K^T
        float sf[8][4];
        #pragma unroll
        for (int f = 0; f < 8; f++)
            #pragma unroll
            for (int e = 0; e < 4; e++) sf[f][e] = 0.f;
        #pragma unroll
        for (int kt = 0; kt < 4; kt++) {
            unsigned bf[8][2];
            #pragma unroll
            for (int jb = 0; jb < 4; jb++) {
                uint32_t addr = kbase + (uint32_t)((jb * 16 + q2 * 8 + tr) * SP_BYTES
                                                   + (kt * 16 + q1 * 8) * 2);
                ldsm_x4(bf[jb * 2][0], bf[jb * 2][1], bf[jb * 2 + 1][0], bf[jb * 2 + 1][1], addr);
            }
            #pragma unroll
            for (int fn = 0; fn < 8; fn++)
                mma_f16(sf[fn], qf[kt], bf[fn][0], bf[fn][1]);
        }

        int base = (W_ - 1 - w) * 64;
        bool far  = (w <= W_ - 6);
        bool last = (w == W_ - 1);
        float mx0 = -1e30f, mx1 = -1e30f;
        if (far) {
            #pragma unroll
            for (int f = 0; f < 8; f++) {
                #pragma unroll
                for (int e = 0; e < 2; e++) {
                    float v0 = fmaf(sf[f][e],     SCALE_LOG2, cb);
                    float v1 = fmaf(sf[f][e + 2], SCALE_LOG2, cb);
                    sf[f][e] = v0; sf[f][e + 2] = v1;
                    mx0 = fmaxf(mx0, v0); mx1 = fmaxf(mx1, v1);
                }
            }
        } else {
            #pragma unroll
            for (int f = 0; f < 8; f++) {
                #pragma unroll
                for (int e = 0; e < 2; e++) {
                    int j = f * 8 + 2 * c + e;
                    int d0 = base + row0 - j;
                    int d1 = d0 + 8;
                    float v0 = fmaf(sf[f][e],     SCALE_LOG2, bias_s[max(min(d0, 256) + 1, 0)]);
                    float v1 = fmaf(sf[f][e + 2], SCALE_LOG2, bias_s[max(min(d1, 256) + 1, 0)]);
                    if (last && d0 < 0) v0 = -1e30f;
                    if (last && d1 < 0) v1 = -1e30f;
                    sf[f][e] = v0; sf[f][e + 2] = v1;
                    mx0 = fmaxf(mx0, v0); mx1 = fmaxf(mx1, v1);
                }
            }
        }
        mx0 = fmaxf(mx0, __shfl_xor_sync(0xffffffffu, mx0, 1));
        mx0 = fmaxf(mx0, __shfl_xor_sync(0xffffffffu, mx0, 2));
        mx1 = fmaxf(mx1, __shfl_xor_sync(0xffffffffu, mx1, 1));
        mx1 = fmaxf(mx1, __shfl_xor_sync(0xffffffffu, mx1, 2));
        float mn0 = fmaxf(m0, mx0), mn1 = fmaxf(m1, mx1);
        float sc0 = exp2f(m0 - mn0), sc1 = exp2f(m1 - mn1);
        m0 = mn0; m1 = mn1;

        unsigned pa[4][4];
        float s0 = 0.f, s1 = 0.f;
        #pragma unroll
        for (int f = 0; f < 8; f++) {
            float p00 = exp2f(sf[f][0] - mn0);
            float p01 = exp2f(sf[f][1] - mn0);
            float p10 = exp2f(sf[f][2] - mn1);
            float p11 = exp2f(sf[f][3] - mn1);
            s0 += p00 + p01; s1 += p10 + p11;
            pa[f >> 1][(f & 1) * 2 + 0] = pack_h2(p00, p01);
            pa[f >> 1][(f & 1) * 2 + 1] = pack_h2(p10, p11);
        }
        s0 += __shfl_xor_sync(0xffffffffu, s0, 1);
        s0 += __shfl_xor_sync(0xffffffffu, s0, 2);
        s1 += __shfl_xor_sync(0xffffffffu, s1, 1);
        s1 += __shfl_xor_sync(0xffffffffu, s1, 2);
        l0 = l0 * sc0 + s0;
        l1 = l1 * sc1 + s1;
        #pragma unroll
        for (int f = 0; f < 8; f++) {
            of[f][0] *= sc0; of[f][1] *= sc0;
            of[f][2] *= sc1; of[f][3] *= sc1;
        }

        // O += P @ V
        #pragma unroll
        for (int kt = 0; kt < 4; kt++) {
            unsigned bf[8][2];
            #pragma unroll
            for (int fn2 = 0; fn2 < 4; fn2++) {
                uint32_t addr = vbase + (uint32_t)((kt * 16 + tr + q1 * 8) * SP_BYTES
                                                   + (fn2 * 16 + q2 * 8) * 2);
                ldsm_x4_t(bf[fn2 * 2][0], bf[fn2 * 2][1], bf[fn2 * 2 + 1][0], bf[fn2 * 2 + 1][1], addr);
            }
            #pragma unroll
            for (int fn = 0; fn < 8; fn++)
                mma_f16(of[fn], pa[kt], bf[fn][0], bf[fn][1]);
        }

        if (w + 1 < hi) {
            asm volatile("cp.async.wait_group 0;" ::: "memory");
            __syncthreads();
        }
        buf ^= 1;
    }

    float* OPz = OP + (size_t)z * L_ * DM_;
    #pragma unroll
    for (int f = 0; f < 8; f++) {
        int col = f * 8 + 2 * c;
        *(float2*)(OPz + (size_t)(n * 64 + row0) * DM_ + h * 64 + col) =
            make_float2(of[f][0], of[f][1]);
        *(float2*)(OPz + (size_t)(n * 64 + row0 + 8) * DM_ + h * 64 + col) =
            make_float2(of[f][2], of[f][3]);
    }
    if (c == 0) {
        Mz[row0] = m0;     Lz[row0] = l0;
        Mz[row0 + 8] = m1; Lz[row0 + 8] = l1;
    }
}

// ---------------- combine split-KV partials -> half O ----------------
__global__ __launch_bounds__(256) void combine_attn(const float* __restrict__ OP,
                                                    const float* __restrict__ Mp,
                                                    const float* __restrict__ Lp,
                                                    __half* __restrict__ O) {
    size_t idx = ((size_t)blockIdx.x * 256 + threadIdx.x) * 8;
    int row = (int)(idx >> 10);
    int col = (int)(idx & (DM_ - 1));
    int h = col >> 6;
    size_t mi = (size_t)h * L_ + row;
    float m0 = Mp[mi], m1 = Mp[(size_t)H_ * L_ + mi];
    float l0 = Lp[mi], l1 = Lp[(size_t)H_ * L_ + mi];
    float m = fmaxf(m0, m1);
    float a0 = exp2f(m0 - m), a1 = exp2f(m1 - m);
    float invl = 1.f / (l0 * a0 + l1 * a1);
    float w0 = a0 * invl, w1 = a1 * invl;
    float4 x0 = *(const float4*)(OP + idx);
    float4 x1 = *(const float4*)(OP + idx + 4);
    float4 y0 = *(const float4*)(OP + (size_t)L_ * DM_ + idx);
    float4 y1 = *(const float4*)(OP + (size_t)L_ * DM_ + idx + 4);
    uint4 o;
    o.x = pack_h2(x0.x * w0 + y0.x * w1, x0.y * w0 + y0.y * w1);
    o.y = pack_h2(x0.z * w0 + y0.z * w1, x0.w * w0 + y0.w * w1);
    o.z = pack_h2(x1.x * w0 + y1.x * w1, x1.y * w0 + y1.y * w1);
    o.w = pack_h2(x1.z * w0 + y1.z * w1, x1.w * w0 + y1.w * w1);
    *(uint4*)(O + idx) = o;
}

// ---------------- launch ----------------
extern "C" void kernel_launch(void* const* d_in, const int* in_sizes, int n_in,
                              void* d_out, int out_size) {
    (void)in_sizes; (void)n_in; (void)out_size;
    const float* x      = (const float*)d_in[0];
    const float* Wq     = (const float*)d_in[1];
    const float* Wk     = (const float*)d_in[2];
    const float* Wv     = (const float*)d_in[3];
    const float* Wo     = (const float*)d_in[4];
    const float* rel    = (const float*)d_in[5];
    const float* ln1g   = (const float*)d_in[6];
    const float* ln1b   = (const float*)d_in[7];
    const float* ln2g   = (const float*)d_in[8];
    const float* ln2b   = (const float*)d_in[9];
    const float* W1     = (const float*)d_in[10];
    const float* b1     = (const float*)d_in[11];
    const float* W2     = (const float*)d_in[12];
    const float* b2     = (const float*)d_in[13];
    float* out = (float*)d_out;

    __half *Hb, *Qb, *Kb, *Vb, *Ob, *Gb;
    float *X1, *OP, *Mp, *Lp;
    __half *WqH, *WkH, *WvH, *WoH, *W1H, *W2H;
    cudaGetSymbolAddress((void**)&Hb, g_H);
    cudaGetSymbolAddress((void**)&Qb, g_Q);
    cudaGetSymbolAddress((void**)&Kb, g_K);
    cudaGetSymbolAddress((void**)&Vb, g_V);
    cudaGetSymbolAddress((void**)&Ob, g_O);
    cudaGetSymbolAddress((void**)&X1, g_X1);
    cudaGetSymbolAddress((void**)&Gb, g_G);
    cudaGetSymbolAddress((void**)&OP, g_OP);
    cudaGetSymbolAddress((void**)&Mp, g_Mp);
    cudaGetSymbolAddress((void**)&Lp, g_Lp);
    cudaGetSymbolAddress((void**)&WqH, g_WqH);
    cudaGetSymbolAddress((void**)&WkH, g_WkH);
    cudaGetSymbolAddress((void**)&WvH, g_WvH);
    cudaGetSymbolAddress((void**)&WoH, g_WoH);
    cudaGetSymbolAddress((void**)&W1H, g_W1H);
    cudaGetSymbolAddress((void**)&W2H, g_W2H);

    cudaFuncSetAttribute(attn_h, cudaFuncAttributeMaxDynamicSharedMemorySize, ATTN_SMEM);
    cudaFuncSetAttribute(hgemm_pipe<false, false, false, true>,  cudaFuncAttributeMaxDynamicSharedMemorySize, PIPE_SMEM);
    cudaFuncSetAttribute(hgemm_pipe<false, true, false, false>,  cudaFuncAttributeMaxDynamicSharedMemorySize, PIPE_SMEM);
    cudaFuncSetAttribute(hgemm_pipe<true, false, true, true>,    cudaFuncAttributeMaxDynamicSharedMemorySize, PIPE_SMEM);
    cudaFuncSetAttribute(hgemm_pipe<true, true, false, false>,   cudaFuncAttributeMaxDynamicSharedMemorySize, PIPE_SMEM);

    // 0+1. fused: LN1 + convert all weights (one launch)
    prep<<<L_ + CVT_BLOCKS, 256>>>(x, ln1g, ln1b, Hb,
                                   Wq, Wk, Wv, Wo, W1, W2,
                                   WqH, WkH, WvH, WoH, W1H, W2H);

    // 2. fused Q,K,V GEMMs
    hgemm_pipe<false, false, false, true><<<dim3(DM_ / 128, L_ / 128, 3), 256, PIPE_SMEM>>>(
        Hb, WqH, WkH, WvH, Qb, Kb, Vb, nullptr, nullptr, L_, DM_, DM_);

    // 3. split-KV banded attention + combine
    attn_h<<<dim3(NB_, H_, 2), 128, ATTN_SMEM>>>(Qb, Kb, Vb, rel, OP, Mp, Lp);
    combine_attn<<<L_ * DM_ / 8 / 256, 256>>>(OP, Mp, Lp, Ob);

    // 4. x1 = x + O @ Wo
    hgemm_pipe<false, true, false, false><<<dim3(DM_ / 128, L_ / 128, 1), 256, PIPE_SMEM>>>(
        Ob, WoH, WoH, WoH, X1, X1, X1, nullptr, x, L_, DM_, DM_);

    // 5. h2 = LN2(x1)
    ln_kernel<<<L_, 256>>>(X1, ln2g, ln2b, Hb);

    // 6. G = gelu(h2 @ W1 + b1)
    hgemm_pipe<true, false, true, true><<<dim3(DFF_ / 128, L_ / 128, 1), 256, PIPE_SMEM>>>(
        Hb, W1H, W1H, W1H, Gb, Gb, Gb, b1, nullptr, L_, DFF_, DM_);

    // 7. out = x1 + G @ W2 + b2
    hgemm_pipe<true, true, false, false><<<dim3(DM_ / 128, L_ / 128, 1), 256, PIPE_SMEM>>>(
        Gb, W2H, W2H, W2H, out, out, out, b2, X1, L_, DM_, DFF_);
}

// round 17
// speedup vs baseline: 1.0219x; 1.0219x over previous
#include <cuda_runtime.h>
#include <cuda_fp16.h>
#include <stdint.h>
#include <math.h>

#define L_   4096
#define DM_  1024
#define H_   16
#define DH_  64
#define BS_  64
#define W_   16
#define NB_  64
#define DFF_ 4096

// ---------------- scratch (static __device__ arrays; no allocations) ----------------
__device__ __half g_H [L_ * DM_];
__device__ __half g_Q [L_ * DM_];
__device__ __half g_K [L_ * DM_];
__device__ __half g_V [L_ * DM_];
__device__ __half g_O [L_ * DM_];
__device__ float  g_X1[L_ * DM_];
__device__ __half g_G [L_ * DFF_];
__device__ __half g_WqH[DM_ * DM_];
__device__ __half g_WkH[DM_ * DM_];
__device__ __half g_WvH[DM_ * DM_];
__device__ __half g_WoH[DM_ * DM_];
__device__ __half g_W1H[DM_ * DFF_];
__device__ __half g_W2H[DFF_ * DM_];

// ---------------- small helpers ----------------
__device__ __forceinline__ float block_sum(float val, float* red) {
    int t = threadIdx.x;
    #pragma unroll
    for (int o = 16; o > 0; o >>= 1) val += __shfl_xor_sync(0xffffffffu, val, o);
    __syncthreads();
    if ((t & 31) == 0) red[t >> 5] = val;
    __syncthreads();
    if (t == 0) {
        float z = 0.f;
        #pragma unroll
        for (int i = 0; i < 8; i++) z += red[i];
        red[0] = z;
    }
    __syncthreads();
    return red[0];
}

__device__ __forceinline__ float gelu_f(float x) {
    float x3 = x * x * x;
    return 0.5f * x * (1.f + tanhf(0.7978845608028654f * (x + 0.044715f * x3)));
}

__device__ __forceinline__ void mma_f16(float* d, const unsigned* a, unsigned b0, unsigned b1) {
    asm volatile(
        "mma.sync.aligned.m16n8k16.row.col.f32.f16.f16.f32 "
        "{%0,%1,%2,%3}, {%4,%5,%6,%7}, {%8,%9}, {%0,%1,%2,%3};\n"
        : "+f"(d[0]), "+f"(d[1]), "+f"(d[2]), "+f"(d[3])
        : "r"(a[0]), "r"(a[1]), "r"(a[2]), "r"(a[3]), "r"(b0), "r"(b1));
}

__device__ __forceinline__ void ldsm_x4(unsigned& r0, unsigned& r1, unsigned& r2, unsigned& r3,
                                        uint32_t addr) {
    asm volatile("ldmatrix.sync.aligned.m8n8.x4.shared.b16 {%0,%1,%2,%3}, [%4];"
                 : "=r"(r0), "=r"(r1), "=r"(r2), "=r"(r3) : "r"(addr));
}
__device__ __forceinline__ void ldsm_x4_t(unsigned& r0, unsigned& r1, unsigned& r2, unsigned& r3,
                                          uint32_t addr) {
    asm volatile("ldmatrix.sync.aligned.m8n8.x4.trans.shared.b16 {%0,%1,%2,%3}, [%4];"
                 : "=r"(r0), "=r"(r1), "=r"(r2), "=r"(r3) : "r"(addr));
}

__device__ __forceinline__ uint32_t s2u(const void* p) {
    return (uint32_t)__cvta_generic_to_shared(p);
}

__device__ __forceinline__ void cp16(uint32_t dst, const void* src) {
    asm volatile("cp.async.cg.shared.global [%0], [%1], 16;" :: "r"(dst), "l"(src));
}

__device__ __forceinline__ uint32_t pack_h2(float lo, float hi) {
    __half2 h = __floats2half2_rn(lo, hi);
    return *reinterpret_cast<uint32_t*>(&h);
}

// ---------------- LayerNorm body (shared by prep + ln_kernel) ----------------
__device__ __forceinline__ void ln_row(const float* __restrict__ x,
                                       const float* __restrict__ g,
                                       const float* __restrict__ b,
                                       __half* __restrict__ out, int row, float* red) {
    const float* xr = x + (size_t)row * DM_;
    int t = threadIdx.x;
    float v[4];
    float s = 0.f;
    #pragma unroll
    for (int i = 0; i < 4; i++) { v[i] = xr[t + i * 256]; s += v[i]; }
    float mean = block_sum(s, red) * (1.f / DM_);
    float s2 = 0.f;
    #pragma unroll
    for (int i = 0; i < 4; i++) { float d = v[i] - mean; s2 += d * d; }
    float var = block_sum(s2, red) * (1.f / DM_);
    float inv = rsqrtf(var + 1e-5f);
    __half* orow = out + (size_t)row * DM_;
    #pragma unroll
    for (int i = 0; i < 4; i++) {
        int c = t + i * 256;
        orow[c] = __float2half((v[i] - mean) * inv * g[c] + b[c]);
    }
}

__global__ __launch_bounds__(256) void ln_kernel(const float* __restrict__ x,
                                                 const float* __restrict__ g,
                                                 const float* __restrict__ b,
                                                 __half* __restrict__ out) {
    __shared__ float red[8];
    ln_row(x, g, b, out, blockIdx.x, red);
}

// ---------------- fused prep: LN1 (blocks < L_) + weight cvt (blocks >= L_) ----------
#define SMALL8 (DM_ * DM_ / 8)
#define CVT_BLOCKS (12 * SMALL8 / 256)
__global__ __launch_bounds__(256) void prep(
        const float* __restrict__ x, const float* __restrict__ g1,
        const float* __restrict__ b1g, __half* __restrict__ Hout,
        const float* __restrict__ s0, const float* __restrict__ s1,
        const float* __restrict__ s2, const float* __restrict__ s3,
        const float* __restrict__ s4, const float* __restrict__ s5,
        __half* __restrict__ d0, __half* __restrict__ d1,
        __half* __restrict__ d2, __half* __restrict__ d3,
        __half* __restrict__ d4, __half* __restrict__ d5) {
    __shared__ float red[8];
    if (blockIdx.x < L_) {
        ln_row(x, g1, b1g, Hout, blockIdx.x, red);
        return;
    }
    long i = (long)(blockIdx.x - L_) * 256 + threadIdx.x;
    const float* src; __half* dst; long off;
    if      (i < 1 * SMALL8)  { src = s0; dst = d0; off = i; }
    else if (i < 2 * SMALL8)  { src = s1; dst = d1; off = i - 1 * SMALL8; }
    else if (i < 3 * SMALL8)  { src = s2; dst = d2; off = i - 2 * SMALL8; }
    else if (i < 4 * SMALL8)  { src = s3; dst = d3; off = i - 3 * SMALL8; }
    else if (i < 8 * SMALL8)  { src = s4; dst = d4; off = i - 4 * SMALL8; }
    else                      { src = s5; dst = d5; off = i - 8 * SMALL8; }
    long e = off * 8;
    float4 a = *(const float4*)(src + e);
    float4 b = *(const float4*)(src + e + 4);
    uint4 o;
    o.x = pack_h2(a.x, a.y); o.y = pack_h2(a.z, a.w);
    o.z = pack_h2(b.x, b.y); o.w = pack_h2(b.z, b.w);
    *(uint4*)(dst + e) = o;
}

// ---------------- ldmatrix fp16 GEMM, BK=64, 256 thr, warp tile 32x64 ----------------
#define A_STAGE_BYTES (128 * 144)
#define B_STAGE_BYTES (64 * 272)
#define STAGE_BYTES (A_STAGE_BYTES + B_STAGE_BYTES)
#define PIPE_SMEM (3 * STAGE_BYTES)

template<bool BIAS, bool RES, bool GELU_, bool HOUT>
__global__ __launch_bounds__(256, 2) void hgemm_pipe(
        const __half* __restrict__ A,
        const __half* __restrict__ B0, const __half* __restrict__ B1, const __half* __restrict__ B2,
        void* __restrict__ C0, void* __restrict__ C1, void* __restrict__ C2,
        const float* __restrict__ bias,
        const float* __restrict__ res,
        int M, int N, int K) {
    extern __shared__ char smem_c[];
    uint32_t sb = s2u(smem_c);

    int tid  = threadIdx.x;
    int lane = tid & 31;
    int wid  = tid >> 5;
    int bm = blockIdx.y * 128, bn = blockIdx.x * 128;
    int wm = wid >> 1, wn = wid & 1;
    int r = lane >> 2, c = lane & 3;

    const __half* B = (blockIdx.z == 0) ? B0 : (blockIdx.z == 1) ? B1 : B2;
    void*         C = (blockIdx.z == 0) ? C0 : (blockIdx.z == 1) ? C1 : C2;

    float acc[2][8][4];
    #pragma unroll
    for (int fm = 0; fm < 2; fm++)
        #pragma unroll
        for (int fn = 0; fn < 8; fn++)
            #pragma unroll
            for (int i = 0; i < 4; i++) acc[fm][fn][i] = 0.f;

    int NIT = K >> 6;

    auto issue = [&](int it) {
        uint32_t base = sb + (uint32_t)(it % 3) * STAGE_BYTES;
        int k0 = it << 6;
        #pragma unroll
        for (int p = 0; p < 4; p++) {
            int idx = p * 256 + tid;
            int row = idx >> 3, aq = idx & 7;
            cp16(base + (uint32_t)(row * 144 + aq * 16),
                 A + (size_t)(bm + row) * K + k0 + aq * 8);
        }
        #pragma unroll
        for (int p = 0; p < 4; p++) {
            int idx = p * 256 + tid;
            int row = idx >> 4, nq = idx & 15;
            cp16(base + (uint32_t)(A_STAGE_BYTES + row * 272 + nq * 16),
                 B + (size_t)(k0 + row) * N + bn + nq * 8);
        }
        asm volatile("cp.async.commit_group;" ::: "memory");
    };

    issue(0);
    issue(1);

    int tr = lane & 7;
    int q1 = (lane >> 3) & 1;
    int q2 = lane >> 4;

    for (int it = 0; it < NIT; it++) {
        asm volatile("cp.async.wait_group 1;" ::: "memory");
        __syncthreads();
        if (it + 2 < NIT) issue(it + 2);
        else asm volatile("cp.async.commit_group;" ::: "memory");

        uint32_t abase = sb + (uint32_t)(it % 3) * STAGE_BYTES;
        uint32_t bbase = abase + A_STAGE_BYTES;

        #pragma unroll
        for (int kt = 0; kt < 4; kt++) {
            unsigned af[2][4], bf[8][2];
            #pragma unroll
            for (int fm = 0; fm < 2; fm++) {
                int row = wm * 32 + fm * 16 + tr + q1 * 8;
                int colh = kt * 16 + q2 * 8;
                ldsm_x4(af[fm][0], af[fm][1], af[fm][2], af[fm][3],
                        abase + (uint32_t)(row * 144 + colh * 2));
            }
            #pragma unroll
            for (int fn2 = 0; fn2 < 4; fn2++) {
                int kk = kt * 16 + tr + q1 * 8;
                int nn = wn * 64 + fn2 * 16 + q2 * 8;
                ldsm_x4_t(bf[fn2 * 2][0], bf[fn2 * 2][1], bf[fn2 * 2 + 1][0], bf[fn2 * 2 + 1][1],
                          bbase + (uint32_t)(kk * 272 + nn * 2));
            }
            #pragma unroll
            for (int fm = 0; fm < 2; fm++)
                #pragma unroll
                for (int fn = 0; fn < 8; fn++)
                    mma_f16(acc[fm][fn], af[fm], bf[fn][0], bf[fn][1]);
        }
    }

    // epilogue
    #pragma unroll
    for (int fm = 0; fm < 2; fm++) {
        int r_lo = bm + wm * 32 + fm * 16 + r;
        #pragma unroll
        for (int fn = 0; fn < 8; fn++) {
            int col = bn + wn * 64 + fn * 8 + 2 * c;
            float v0 = acc[fm][fn][0], v1 = acc[fm][fn][1];
            float v2 = acc[fm][fn][2], v3 = acc[fm][fn][3];
            if (BIAS) {
                float b0v = bias[col], b1v = bias[col + 1];
                v0 += b0v; v1 += b1v; v2 += b0v; v3 += b1v;
            }
            if (GELU_) { v0 = gelu_f(v0); v1 = gelu_f(v1); v2 = gelu_f(v2); v3 = gelu_f(v3); }
            if (RES) {
                float2 r0 = *(const float2*)(res + (size_t)r_lo * N + col);
                float2 r1 = *(const float2*)(res + (size_t)(r_lo + 8) * N + col);
                v0 += r0.x; v1 += r0.y; v2 += r1.x; v3 += r1.y;
            }
            if (HOUT) {
                __half* Ch = (__half*)C;
                *(uint32_t*)(Ch + (size_t)r_lo * N + col)       = pack_h2(v0, v1);
                *(uint32_t*)(Ch + (size_t)(r_lo + 8) * N + col) = pack_h2(v2, v3);
            } else {
                float* Cf = (float*)C;
                *(float2*)(Cf + (size_t)r_lo * N + col)       = make_float2(v0, v1);
                *(float2*)(Cf + (size_t)(r_lo + 8) * N + col) = make_float2(v2, v3);
            }
        }
    }
}

// ---------------- banded attention: fp16 mma, register P, base-2 softmax (R12) -------
#define SP_BYTES 144
#define TILE_BYTES (64 * SP_BYTES)
#define QP_OFF 0
#define K_OFF  TILE_BYTES
#define V_OFF  (TILE_BYTES * 3)
#define BIAS_OFF (TILE_BYTES * 5)
#define ATTN_SMEM (BIAS_OFF + 258 * 4)
#define LOG2E 1.4426950408889634f
#define SCALE_LOG2 (0.125f * LOG2E)

__global__ __launch_bounds__(128) void attn_h(const __half* __restrict__ Q,
                                              const __half* __restrict__ Kb,
                                              const __half* __restrict__ Vb,
                                              const float* __restrict__ rel_emb,
                                              __half* __restrict__ O) {
    extern __shared__ char sm[];
    uint32_t sb = s2u(sm);
    float* bias_s = (float*)(sm + BIAS_OFF);

    int n = blockIdx.x, h = blockIdx.y;
    int tid = threadIdx.x, lane = tid & 31, wid = tid >> 5;
    int r = lane >> 2, c = lane & 3;
    int tr = lane & 7, q1 = (lane >> 3) & 1, q2 = lane >> 4;

    #pragma unroll
    for (int p = 0; p < 4; p++) {
        int idx = p * 128 + tid;
        int row = idx >> 3, nq = idx & 7;
        cp16(sb + QP_OFF + (uint32_t)(row * SP_BYTES + nq * 16),
             Q + (size_t)(n * 64 + row) * DM_ + h * 64 + nq * 8);
    }
    for (int t = tid; t < 258; t += 128) bias_s[t] = rel_emb[t * H_ + h] * LOG2E;

    int w0 = (n >= W_ - 1) ? 0 : (W_ - 1 - n);

    auto issueKV = [&](int w, int b) {
        int sbk = n - (W_ - 1) + w;
        const __half* kp = Kb + (size_t)(sbk * 64) * DM_ + h * 64;
        const __half* vp = Vb + (size_t)(sbk * 64) * DM_ + h * 64;
        uint32_t kb = sb + K_OFF + (uint32_t)b * TILE_BYTES;
        uint32_t vb = sb + V_OFF + (uint32_t)b * TILE_BYTES;
        #pragma unroll
        for (int p = 0; p < 4; p++) {
            int idx = p * 128 + tid;
            int row = idx >> 3, nq = idx & 7;
            cp16(kb + (uint32_t)(row * SP_BYTES + nq * 16), kp + (size_t)row * DM_ + nq * 8);
            cp16(vb + (uint32_t)(row * SP_BYTES + nq * 16), vp + (size_t)row * DM_ + nq * 8);
        }
        asm volatile("cp.async.commit_group;" ::: "memory");
    };

    issueKV(w0, 0);
    asm volatile("cp.async.wait_group 0;" ::: "memory");
    __syncthreads();

    unsigned qf[4][4];
    {
        int arow = wid * 16 + tr + q1 * 8;
        #pragma unroll
        for (int kt = 0; kt < 4; kt++) {
            int colh = kt * 16 + q2 * 8;
            ldsm_x4(qf[kt][0], qf[kt][1], qf[kt][2], qf[kt][3],
                    sb + QP_OFF + (uint32_t)(arow * SP_BYTES + colh * 2));
        }
    }

    float of[8][4];
    #pragma unroll
    for (int f = 0; f < 8; f++)
        #pragma unroll
        for (int e = 0; e < 4; e++) of[f][e] = 0.f;
    float m0 = -1e30f, m1 = -1e30f, l0 = 0.f, l1 = 0.f;

    int row0 = wid * 16 + r;
    int buf = 0;
    float cb = bias_s[257];

    for (int w = w0; w < W_; w++) {
        if (w + 1 < W_) issueKV(w + 1, buf ^ 1);
        uint32_t kbase = sb + K_OFF + (uint32_t)buf * TILE_BYTES;
        uint32_t vbase = sb + V_OFF + (uint32_t)buf * TILE_BYTES;

        // S = Q @ K^T
        float sf[8][4];
        #pragma unroll
        for (int f = 0; f < 8; f++)
            #pragma unroll
            for (int e = 0; e < 4; e++) sf[f][e] = 0.f;
        #pragma unroll
        for (int kt = 0; kt < 4; kt++) {
            unsigned bf[8][2];
            #pragma unroll
            for (int jb = 0; jb < 4; jb++) {
                uint32_t addr = kbase + (uint32_t)((jb * 16 + q2 * 8 + tr) * SP_BYTES
                                                   + (kt * 16 + q1 * 8) * 2);
                ldsm_x4(bf[jb * 2][0], bf[jb * 2][1], bf[jb * 2 + 1][0], bf[jb * 2 + 1][1], addr);
            }
            #pragma unroll
            for (int fn = 0; fn < 8; fn++)
                mma_f16(sf[fn], qf[kt], bf[fn][0], bf[fn][1]);
        }

        // scale + bias + mask (log2 domain)
        int base = (W_ - 1 - w) * 64;
        bool far  = (w <= W_ - 6);
        bool last = (w == W_ - 1);
        float mx0 = -1e30f, mx1 = -1e30f;
        if (far) {
            #pragma unroll
            for (int f = 0; f < 8; f++) {
                #pragma unroll
                for (int e = 0; e < 2; e++) {
                    float v0 = fmaf(sf[f][e],     SCALE_LOG2, cb);
                    float v1 = fmaf(sf[f][e + 2], SCALE_LOG2, cb);
                    sf[f][e] = v0; sf[f][e + 2] = v1;
                    mx0 = fmaxf(mx0, v0); mx1 = fmaxf(mx1, v1);
                }
            }
        } else {
            #pragma unroll
            for (int f = 0; f < 8; f++) {
                #pragma unroll
                for (int e = 0; e < 2; e++) {
                    int j = f * 8 + 2 * c + e;
                    int d0 = base + row0 - j;
                    int d1 = d0 + 8;
                    float v0 = fmaf(sf[f][e],     SCALE_LOG2, bias_s[max(min(d0, 256) + 1, 0)]);
                    float v1 = fmaf(sf[f][e + 2], SCALE_LOG2, bias_s[max(min(d1, 256) + 1, 0)]);
                    if (last && d0 < 0) v0 = -1e30f;
                    if (last && d1 < 0) v1 = -1e30f;
                    sf[f][e] = v0; sf[f][e + 2] = v1;
                    mx0 = fmaxf(mx0, v0); mx1 = fmaxf(mx1, v1);
                }
            }
        }
        mx0 = fmaxf(mx0, __shfl_xor_sync(0xffffffffu, mx0, 1));
        mx0 = fmaxf(mx0, __shfl_xor_sync(0xffffffffu, mx0, 2));
        mx1 = fmaxf(mx1, __shfl_xor_sync(0xffffffffu, mx1, 1));
        mx1 = fmaxf(mx1, __shfl_xor_sync(0xffffffffu, mx1, 2));
        float mn0 = fmaxf(m0, mx0), mn1 = fmaxf(m1, mx1);
        float sc0 = exp2f(m0 - mn0), sc1 = exp2f(m1 - mn1);
        m0 = mn0; m1 = mn1;

        unsigned pa[4][4];
        float s0 = 0.f, s1 = 0.f;
        #pragma unroll
        for (int f = 0; f < 8; f++) {
            float p00 = exp2f(sf[f][0] - mn0);
            float p01 = exp2f(sf[f][1] - mn0);
            float p10 = exp2f(sf[f][2] - mn1);
            float p11 = exp2f(sf[f][3] - mn1);
            s0 += p00 + p01; s1 += p10 + p11;
            pa[f >> 1][(f & 1) * 2 + 0] = pack_h2(p00, p01);
            pa[f >> 1][(f & 1) * 2 + 1] = pack_h2(p10, p11);
        }
        s0 += __shfl_xor_sync(0xffffffffu, s0, 1);
        s0 += __shfl_xor_sync(0xffffffffu, s0, 2);
        s1 += __shfl_xor_sync(0xffffffffu, s1, 1);
        s1 += __shfl_xor_sync(0xffffffffu, s1, 2);
        l0 = l0 * sc0 + s0;
        l1 = l1 * sc1 + s1;
        #pragma unroll
        for (int f = 0; f < 8; f++) {
            of[f][0] *= sc0; of[f][1] *= sc0;
            of[f][2] *= sc1; of[f][3] *= sc1;
        }

        // O += P @ V
        #pragma unroll
        for (int kt = 0; kt < 4; kt++) {
            unsigned bf[8][2];
            #pragma unroll
            for (int fn2 = 0; fn2 < 4; fn2++) {
                uint32_t addr = vbase + (uint32_t)((kt * 16 + tr + q1 * 8) * SP_BYTES
                                                   + (fn2 * 16 + q2 * 8) * 2);
                ldsm_x4_t(bf[fn2 * 2][0], bf[fn2 * 2][1], bf[fn2 * 2 + 1][0], bf[fn2 * 2 + 1][1], addr);
            }
            #pragma unroll
            for (int fn = 0; fn < 8; fn++)
                mma_f16(of[fn], pa[kt], bf[fn][0], bf[fn][1]);
        }

        if (w + 1 < W_) {
            asm volatile("cp.async.wait_group 0;" ::: "memory");
            __syncthreads();
        }
        buf ^= 1;
    }

    float invl0 = 1.f / l0, invl1 = 1.f / l1;
    #pragma unroll
    for (int f = 0; f < 8; f++) {
        int col = f * 8 + 2 * c;
        *(uint32_t*)(O + (size_t)(n * 64 + row0) * DM_ + h * 64 + col) =
            pack_h2(of[f][0] * invl0, of[f][1] * invl0);
        *(uint32_t*)(O + (size_t)(n * 64 + row0 + 8) * DM_ + h * 64 + col) =
            pack_h2(of[f][2] * invl1, of[f][3] * invl1);
    }
}

// ---------------- launch ----------------
extern "C" void kernel_launch(void* const* d_in, const int* in_sizes, int n_in,
                              void* d_out, int out_size) {
    (void)in_sizes; (void)n_in; (void)out_size;
    const float* x      = (const float*)d_in[0];
    const float* Wq     = (const float*)d_in[1];
    const float* Wk     = (const float*)d_in[2];
    const float* Wv     = (const float*)d_in[3];
    const float* Wo     = (const float*)d_in[4];
    const float* rel    = (const float*)d_in[5];
    const float* ln1g   = (const float*)d_in[6];
    const float* ln1b   = (const float*)d_in[7];
    const float* ln2g   = (const float*)d_in[8];
    const float* ln2b   = (const float*)d_in[9];
    const float* W1     = (const float*)d_in[10];
    const float* b1     = (const float*)d_in[11];
    const float* W2     = (const float*)d_in[12];
    const float* b2     = (const float*)d_in[13];
    float* out = (float*)d_out;

    __half *Hb, *Qb, *Kb, *Vb, *Ob, *Gb;
    float *X1;
    __half *WqH, *WkH, *WvH, *WoH, *W1H, *W2H;
    cudaGetSymbolAddress((void**)&Hb, g_H);
    cudaGetSymbolAddress((void**)&Qb, g_Q);
    cudaGetSymbolAddress((void**)&Kb, g_K);
    cudaGetSymbolAddress((void**)&Vb, g_V);
    cudaGetSymbolAddress((void**)&Ob, g_O);
    cudaGetSymbolAddress((void**)&X1, g_X1);
    cudaGetSymbolAddress((void**)&Gb, g_G);
    cudaGetSymbolAddress((void**)&WqH, g_WqH);
    cudaGetSymbolAddress((void**)&WkH, g_WkH);
    cudaGetSymbolAddress((void**)&WvH, g_WvH);
    cudaGetSymbolAddress((void**)&WoH, g_WoH);
    cudaGetSymbolAddress((void**)&W1H, g_W1H);
    cudaGetSymbolAddress((void**)&W2H, g_W2H);

    cudaFuncSetAttribute(attn_h, cudaFuncAttributeMaxDynamicSharedMemorySize, ATTN_SMEM);
    cudaFuncSetAttribute(hgemm_pipe<false, false, false, true>,  cudaFuncAttributeMaxDynamicSharedMemorySize, PIPE_SMEM);
    cudaFuncSetAttribute(hgemm_pipe<false, true, false, false>,  cudaFuncAttributeMaxDynamicSharedMemorySize, PIPE_SMEM);
    cudaFuncSetAttribute(hgemm_pipe<true, false, true, true>,    cudaFuncAttributeMaxDynamicSharedMemorySize, PIPE_SMEM);
    cudaFuncSetAttribute(hgemm_pipe<true, true, false, false>,   cudaFuncAttributeMaxDynamicSharedMemorySize, PIPE_SMEM);

    // 0+1. fused: LN1 + convert all weights (one launch)
    prep<<<L_ + CVT_BLOCKS, 256>>>(x, ln1g, ln1b, Hb,
                                   Wq, Wk, Wv, Wo, W1, W2,
                                   WqH, WkH, WvH, WoH, W1H, W2H);

    // 2. fused Q,K,V GEMMs
    hgemm_pipe<false, false, false, true><<<dim3(DM_ / 128, L_ / 128, 3), 256, PIPE_SMEM>>>(
        Hb, WqH, WkH, WvH, Qb, Kb, Vb, nullptr, nullptr, L_, DM_, DM_);

    // 3. banded attention (un-split, R12 config)
    attn_h<<<dim3(NB_, H_), 128, ATTN_SMEM>>>(Qb, Kb, Vb, rel, Ob);

    // 4. x1 = x + O @ Wo
    hgemm_pipe<false, true, false, false><<<dim3(DM_ / 128, L_ / 128, 1), 256, PIPE_SMEM>>>(
        Ob, WoH, WoH, WoH, X1, X1, X1, nullptr, x, L_, DM_, DM_);

    // 5. h2 = LN2(x1)
    ln_kernel<<<L_, 256>>>(X1, ln2g, ln2b, Hb);

    // 6. G = gelu(h2 @ W1 + b1)
    hgemm_pipe<true, false, true, true><<<dim3(DFF_ / 128, L_ / 128, 1), 256, PIPE_SMEM>>>(
        Hb, W1H, W1H, W1H, Gb, Gb, Gb, b1, nullptr, L_, DFF_, DM_);

    // 7. out = x1 + G @ W2 + b2
    hgemm_pipe<true, true, false, false><<<dim3(DM_ / 128, L_ / 128, 1), 256, PIPE_SMEM>>>(
        Gb, W2H, W2H, W2H, out, out, out, b2, X1, L_, DM_, DFF_);
}